// round 16
// baseline (speedup 1.0000x reference)
#include <cuda_runtime.h>
#include <cuda_bf16.h>
#include <math.h>
#include <stdint.h>

// Problem sizes (fixed)
#define BB 64     // batch
#define SS 512    // seq len
#define DD 512    // input dim
#define HH 512    // hidden

// ---------------------------------------------------------------------------
// Device scratch (allocation-free rule: device globals only)
// ---------------------------------------------------------------------------
__device__ float g_gi[(size_t)SS * BB * 3 * HH];   // [s][b][3H]
__device__ float g_f [(size_t)SS * BB * 2 * HH];   // [s][b][2H]
__device__ __nv_bfloat16 g_hh[2][BB * HH];         // h hi-plane ping-pong
__device__ __nv_bfloat16 g_hl[2][BB * HH];         // h lo-plane ping-pong
__device__ unsigned g_bar[4];                      // per-batch-group barrier

// ---------------------------------------------------------------------------
// mma.sync helpers (sm_80+ vocabulary — works under compute_103 PTX)
// ---------------------------------------------------------------------------
__device__ __forceinline__ uint32_t smem_to_u32(const void* p) {
    uint32_t a;
    asm("{ .reg .u64 t; cvta.to.shared.u64 t, %1; cvt.u32.u64 %0, t; }"
        : "=r"(a) : "l"(p));
    return a;
}

#define LDMATRIX_X4(r, addr) \
    asm volatile("ldmatrix.sync.aligned.m8n8.x4.shared.b16 {%0,%1,%2,%3}, [%4];" \
        : "=r"((r)[0]), "=r"((r)[1]), "=r"((r)[2]), "=r"((r)[3]) : "r"(addr))

#define MMA_BF16(d, a, b0, b1) \
    asm volatile("mma.sync.aligned.m16n8k16.row.col.f32.bf16.bf16.f32 " \
        "{%0,%1,%2,%3}, {%4,%5,%6,%7}, {%8,%9}, {%0,%1,%2,%3};" \
        : "+f"((d)[0]), "+f"((d)[1]), "+f"((d)[2]), "+f"((d)[3]) \
        : "r"((a)[0]), "r"((a)[1]), "r"((a)[2]), "r"((a)[3]), \
          "r"(b0), "r"(b1))

__device__ __forceinline__ uint32_t pack_bf16(float a, float b) {
    return ((uint32_t)__bfloat16_as_ushort(__float2bfloat16_rn(b)) << 16) |
           (uint32_t)__bfloat16_as_ushort(__float2bfloat16_rn(a));
}

// ---------------------------------------------------------------------------
// Precompute GEMMs: CTA 256(M)x128(N), BK=64, 512 threads (16 warps, 4x4 warp
// grid, warp tile 64x32). bf16 hi/lo 3-pass split. Double-buffered, one sync
// per 64-K chunk. 4 warps/SMSP for tensor-pipe overlap (prev config had 2).
// n-tile fastest in grid.x for L2 A-block sharing.
// ---------------------------------------------------------------------------
#define GP2 72                             // smem pitch in bf16 (144 B rows)
#define GA_TILE_B (256 * GP2 * 2)          // 36864 (A hi or lo)
#define GB_TILE_B (128 * GP2 * 2)          // 18432 (B hi or lo)
#define STG_B (2 * GA_TILE_B + 2 * GB_TILE_B)  // 110592 per stage
#define OFF_AH3(st) ((st) * STG_B)
#define OFF_AL3(st) ((st) * STG_B + GA_TILE_B)
#define OFF_BH3(st) ((st) * STG_B + 2 * GA_TILE_B)
#define OFF_BL3(st) ((st) * STG_B + 2 * GA_TILE_B + GB_TILE_B)
#define GEMM_SMEM_BYTES (2 * STG_B)        // 221184

// A chunk [256 x 64] fp32 = 4096 float4; 8 per thread at 512 threads.
__device__ __forceinline__ void ldg_a(const float* __restrict__ src,
                                      float4 v[8], int t) {
#pragma unroll
    for (int i = 0; i < 8; i++) {
        int idx = t + 512 * i;
        int row = idx >> 4;
        int kq  = idx & 15;
        v[i] = *(const float4*)(src + (size_t)row * 512 + kq * 4);
    }
}

// B chunk [128 x 64] fp32 = 2048 float4; 4 per thread.
__device__ __forceinline__ void ldg_b(const float* __restrict__ src,
                                      float4 v[4], int t) {
#pragma unroll
    for (int i = 0; i < 4; i++) {
        int idx = t + 512 * i;
        int row = idx >> 4;
        int kq  = idx & 15;
        v[i] = *(const float4*)(src + (size_t)row * 512 + kq * 4);
    }
}

__device__ __forceinline__ void cvt_store(char* smem, int hi_off, int lo_off,
                                          float4 x, int row, int kq) {
    float hx = __bfloat162float(__float2bfloat16_rn(x.x));
    float hy = __bfloat162float(__float2bfloat16_rn(x.y));
    float hz = __bfloat162float(__float2bfloat16_rn(x.z));
    float hw = __bfloat162float(__float2bfloat16_rn(x.w));
    uint2 hi = make_uint2(pack_bf16(x.x, x.y), pack_bf16(x.z, x.w));
    uint2 lo = make_uint2(pack_bf16(x.x - hx, x.y - hy),
                          pack_bf16(x.z - hz, x.w - hw));
    uint32_t boff = (uint32_t)(row * GP2 + kq * 4) * 2;
    *(uint2*)(smem + hi_off + boff) = hi;
    *(uint2*)(smem + lo_off + boff) = lo;
}

__device__ __forceinline__ void sts_a(char* smem, int hi_off, int lo_off,
                                      const float4 v[8], int t) {
#pragma unroll
    for (int i = 0; i < 8; i++) {
        int idx = t + 512 * i;
        cvt_store(smem, hi_off, lo_off, v[i], idx >> 4, idx & 15);
    }
}

__device__ __forceinline__ void sts_b(char* smem, int hi_off, int lo_off,
                                      const float4 v[4], int t) {
#pragma unroll
    for (int i = 0; i < 4; i++) {
        int idx = t + 512 * i;
        cvt_store(smem, hi_off, lo_off, v[i], idx >> 4, idx & 15);
    }
}

// One k16 step: warp tile 64(M) x 32(N): 12 ldmatrix.x4 + 48 mma.
__device__ __forceinline__ void warp_k16(uint32_t sb, int st, int ks,
                                         int wm, int wn, int lane,
                                         float acc[4][4][4]) {
    const int lr = lane & 7;
    const int lg = lane >> 3;
    uint32_t ah[4][4], al[4][4];
#pragma unroll
    for (int mt = 0; mt < 4; mt++) {
        int arow = wm * 64 + mt * 16 + lr + (lg & 1) * 8;
        int acol = ks * 16 + (lg >> 1) * 8;
        uint32_t boff = (uint32_t)(arow * GP2 + acol) * 2;
        LDMATRIX_X4(ah[mt], sb + OFF_AH3(st) + boff);
        LDMATRIX_X4(al[mt], sb + OFF_AL3(st) + boff);
    }
    uint32_t bh[2][4], bl[2][4];
#pragma unroll
    for (int np = 0; np < 2; np++) {
        int brow = wn * 32 + np * 16 + lr + (lg >> 1) * 8;
        int bcol = ks * 16 + (lg & 1) * 8;
        uint32_t boff = (uint32_t)(brow * GP2 + bcol) * 2;
        LDMATRIX_X4(bh[np], sb + OFF_BH3(st) + boff);
        LDMATRIX_X4(bl[np], sb + OFF_BL3(st) + boff);
    }
#pragma unroll
    for (int mt = 0; mt < 4; mt++)
#pragma unroll
        for (int np = 0; np < 2; np++)
#pragma unroll
            for (int sub = 0; sub < 2; sub++) {
                int nj = np * 2 + sub;
                MMA_BF16(acc[mt][nj], ah[mt], bh[np][2 * sub], bh[np][2 * sub + 1]);
                MMA_BF16(acc[mt][nj], ah[mt], bl[np][2 * sub], bl[np][2 * sub + 1]);
                MMA_BF16(acc[mt][nj], al[mt], bh[np][2 * sub], bh[np][2 * sub + 1]);
            }
}

__global__ __launch_bounds__(512, 1) void gemm_gi_mma(
    const float* __restrict__ A, const float* __restrict__ W,
    const float* __restrict__ bias)
{
    extern __shared__ char smem[];
    uint32_t sb = smem_to_u32(smem);
    const int t = threadIdx.x;
    const int wid = t >> 5;
    const int lane = t & 31;
    const int wm = wid & 3;            // 4 m-warps x 64 rows = 256
    const int wn = wid >> 2;           // 4 n-warps x 32 cols = 128
    const int m0 = blockIdx.y * 256;   // n fastest: x = n-tile, y = m-tile
    const int n0 = blockIdx.x * 128;

    // Zero the scan's group barrier (replaces the init kernel).
    if (blockIdx.x == 0 && blockIdx.y == 0 && t < 4) g_bar[t] = 0u;

    float acc[4][4][4];
#pragma unroll
    for (int i = 0; i < 4; i++)
#pragma unroll
        for (int j = 0; j < 4; j++)
#pragma unroll
            for (int k = 0; k < 4; k++) acc[i][j][k] = 0.f;

    const float* Abase = A + (size_t)m0 * 512;
    const float* Wbase = W + (size_t)n0 * 512;

    float4 av[8], bv[4];
    ldg_a(Abase, av, t);
    ldg_b(Wbase, bv, t);
    sts_a(smem, OFF_AH3(0), OFF_AL3(0), av, t);
    sts_b(smem, OFF_BH3(0), OFF_BL3(0), bv, t);
    __syncthreads();

    const int NC = 8;   // 512 / 64
    for (int c = 0; c < NC; c++) {
        int st = c & 1;
        if (c + 1 < NC) {
            ldg_a(Abase + (c + 1) * 64, av, t);
            ldg_b(Wbase + (c + 1) * 64, bv, t);
        }
        warp_k16(sb, st, 0, wm, wn, lane, acc);
        warp_k16(sb, st, 1, wm, wn, lane, acc);
        if (c + 1 < NC) {
            int ns = st ^ 1;
            sts_a(smem, OFF_AH3(ns), OFF_AL3(ns), av, t);
            sts_b(smem, OFF_BH3(ns), OFF_BL3(ns), bv, t);
        }
        warp_k16(sb, st, 2, wm, wn, lane, acc);
        warp_k16(sb, st, 3, wm, wn, lane, acc);
        __syncthreads();
    }

    const int qrow = lane >> 2;
    const int qcol = (lane & 3) * 2;
#pragma unroll
    for (int mt = 0; mt < 4; mt++)
#pragma unroll
        for (int half = 0; half < 2; half++) {
            int m = m0 + wm * 64 + mt * 16 + qrow + half * 8;
            int b = m >> 9;
            int s = m & 511;
            float* crow = &g_gi[((size_t)s * 64 + b) * 1536 + n0 + wn * 32];
#pragma unroll
            for (int nj = 0; nj < 4; nj++) {
                int n = nj * 8 + qcol;
                float2 bvv = *(const float2*)&bias[n0 + wn * 32 + n];
                float2 o;
                o.x = acc[mt][nj][half * 2 + 0] + bvv.x;
                o.y = acc[mt][nj][half * 2 + 1] + bvv.y;
                *(float2*)&crow[n] = o;
            }
        }
}

__global__ __launch_bounds__(512, 1) void gemm_f_mma(
    const float* __restrict__ Aux, const float* __restrict__ Wf,
    const float* __restrict__ bf)
{
    extern __shared__ char smem[];
    uint32_t sb = smem_to_u32(smem);
    const int t = threadIdx.x;
    const int wid = t >> 5;
    const int lane = t & 31;
    const int wm = wid & 3;
    const int wn = wid >> 2;
    const int m0 = blockIdx.y * 256;   // n fastest
    const int n0 = blockIdx.x * 128;

    float acc[4][4][4];
#pragma unroll
    for (int i = 0; i < 4; i++)
#pragma unroll
        for (int j = 0; j < 4; j++)
#pragma unroll
            for (int k = 0; k < 4; k++) acc[i][j][k] = 0.f;

    float4 av[8], bv[4];
    ldg_a(Aux + (size_t)m0 * 512, av, t);
    ldg_b(Wf + (size_t)n0 * 512, bv, t);
    sts_a(smem, OFF_AH3(0), OFF_AL3(0), av, t);
    sts_b(smem, OFF_BH3(0), OFF_BL3(0), bv, t);
    __syncthreads();

    const int NC = 16;  // 2 segments x 8 chunks of 64K
    for (int c = 0; c < NC; c++) {
        int st = c & 1;
        if (c + 1 < NC) {
            int cn = c + 1;
            int seg = cn >> 3, kk = cn & 7;
            ldg_a(Aux + (size_t)seg * 32768 * 512 + (size_t)m0 * 512 + kk * 64, av, t);
            ldg_b(Wf + (size_t)seg * 1024 * 512 + (size_t)n0 * 512 + kk * 64, bv, t);
        }
        warp_k16(sb, st, 0, wm, wn, lane, acc);
        warp_k16(sb, st, 1, wm, wn, lane, acc);
        if (c + 1 < NC) {
            int ns = st ^ 1;
            sts_a(smem, OFF_AH3(ns), OFF_AL3(ns), av, t);
            sts_b(smem, OFF_BH3(ns), OFF_BL3(ns), bv, t);
        }
        warp_k16(sb, st, 2, wm, wn, lane, acc);
        warp_k16(sb, st, 3, wm, wn, lane, acc);
        __syncthreads();
    }

    const int qrow = lane >> 2;
    const int qcol = (lane & 3) * 2;
#pragma unroll
    for (int mt = 0; mt < 4; mt++)
#pragma unroll
        for (int half = 0; half < 2; half++) {
            int m = m0 + wm * 64 + mt * 16 + qrow + half * 8;
            int b = m >> 9;
            int s = m & 511;
            float* crow = &g_f[((size_t)s * 64 + b) * 1024 + n0 + wn * 32];
#pragma unroll
            for (int nj = 0; nj < 4; nj++) {
                int n = nj * 8 + qcol;
                int ng = n0 + wn * 32 + n;
                float2 c0 = *(const float2*)&bf[ng];
                float2 c1 = *(const float2*)&bf[1024 + ng];
                float2 o;
                o.x = 0.5f * acc[mt][nj][half * 2 + 0] + 0.5f * (c0.x + c1.x);
                o.y = 0.5f * acc[mt][nj][half * 2 + 1] + 0.5f * (c0.y + c1.y);
                *(float2*)&crow[n] = o;
            }
        }
}

// ---------------------------------------------------------------------------
// Persistent recurrent scan — byte-identical to the round-12 best:
// 256 threads, producer-side bf16 hi/lo h exchange, fused reduce+epilogue,
// t0-spin barrier with __syncthreads detection broadcast.
// Grid 128 = 4 batch-groups (16 b) x 32 column-CTAs (16 hy cols = 48 W rows).
// ---------------------------------------------------------------------------
#define SPITCH 520                       // bf16 pitch
#define S_OFF_WH  0                      // 48 x 520 bf16 = 49920 B
#define S_OFF_WL  49920
#define S_OFF_HH  99840                  // 16 x 520 bf16 = 16640 B
#define S_OFF_HL  116480
#define S_OFF_RED 133120                 // 8 x 784 fp32 = 25088 B
#define S_OFF_BS  158208                 // 48 fp32
#define SCAN_SMEM_BYTES 158400

__global__ __launch_bounds__(256, 1) void scan_kernel(
    const float* __restrict__ hx, const float* __restrict__ Whh,
    const float* __restrict__ bias_hh, float* __restrict__ out)
{
    extern __shared__ char smem[];
    uint32_t sb = smem_to_u32(smem);
    float* redf = (float*)(smem + S_OFF_RED);
    float* bs   = (float*)(smem + S_OFF_BS);

    const int t    = threadIdx.x;
    const int w    = t >> 5;               // warp 0..7 (K-slice 64 each)
    const int lane = t & 31;
    const int lr   = lane & 7;
    const int lg   = lane >> 3;
    const int gid  = blockIdx.x >> 5;
    const int cid  = blockIdx.x & 31;
    const int b0   = gid * 16;
    const int c0   = cid * 16;

    // --- Stage W_hh slice as bf16 hi/lo into smem (once) ---
    for (int i = t; i < 48 * 128; i += 256) {
        int r = i >> 7;
        int q = i & 127;
        int gate = r >> 4, j = r & 15;
        float4 v = *(const float4*)&Whh[(size_t)(gate * 512 + c0 + j) * 512 + q * 4];
        float hx0 = __bfloat162float(__float2bfloat16_rn(v.x));
        float hy0 = __bfloat162float(__float2bfloat16_rn(v.y));
        float hz0 = __bfloat162float(__float2bfloat16_rn(v.z));
        float hw0 = __bfloat162float(__float2bfloat16_rn(v.w));
        uint2 hi = make_uint2(pack_bf16(v.x, v.y), pack_bf16(v.z, v.w));
        uint2 lo = make_uint2(pack_bf16(v.x - hx0, v.y - hy0),
                              pack_bf16(v.z - hz0, v.w - hw0));
        uint32_t boff = (uint32_t)(r * SPITCH + q * 4) * 2;
        *(uint2*)(smem + S_OFF_WH + boff) = hi;
        *(uint2*)(smem + S_OFF_WL + boff) = lo;
    }
    if (t < 48) {
        int gate = t >> 4, j = t & 15;
        bs[t] = bias_hh[gate * 512 + c0 + j];
    }
    __syncthreads();

    // --- W fragments in registers: per warp 3 n16-groups x 4 k16 (hi/lo) ---
    uint32_t bfh[3][4][4], bfl[3][4][4];
#pragma unroll
    for (int np = 0; np < 3; np++)
#pragma unroll
        for (int ks = 0; ks < 4; ks++) {
            int brow = np * 16 + lr + (lg >> 1) * 8;
            int bcol = w * 64 + ks * 16 + (lg & 1) * 8;
            uint32_t boff = (uint32_t)(brow * SPITCH + bcol) * 2;
            LDMATRIX_X4(bfh[np][ks], sb + S_OFF_WH + boff);
            LDMATRIX_X4(bfl[np][ks], sb + S_OFF_WL + boff);
        }

    const int eb = t >> 4;                 // epilogue batch 0..15
    const int ej = t & 15;                 // epilogue column 0..15
    const int bglob = b0 + eb;
    const int qrow = lane >> 2;
    const int qcol = (lane & 3) * 2;

    unsigned* barp = &g_bar[gid];

    // hprev carried in register (exact fp32): this thread owns (bglob, c0+ej)
    float hprev = hx[(size_t)bglob * 512 + c0 + ej];

    for (int s = 0; s < 512; s++) {
        if (s == 0) {
            // One-time: convert hx (fp32) into hi/lo planes in smem
            const float* hsrc = hx + (size_t)b0 * 512;
#pragma unroll
            for (int i = 0; i < 8; i++) {
                int idx = t + 256 * i;
                int row = idx >> 7;
                int q   = idx & 127;
                float4 v = *(const float4*)&hsrc[(size_t)row * 512 + q * 4];
                float hx0 = __bfloat162float(__float2bfloat16_rn(v.x));
                float hy0 = __bfloat162float(__float2bfloat16_rn(v.y));
                float hz0 = __bfloat162float(__float2bfloat16_rn(v.z));
                float hw0 = __bfloat162float(__float2bfloat16_rn(v.w));
                uint2 hi = make_uint2(pack_bf16(v.x, v.y), pack_bf16(v.z, v.w));
                uint2 lo = make_uint2(pack_bf16(v.x - hx0, v.y - hy0),
                                      pack_bf16(v.z - hz0, v.w - hw0));
                uint32_t boff = (uint32_t)(row * SPITCH + q * 4) * 2;
                *(uint2*)(smem + S_OFF_HH + boff) = hi;
                *(uint2*)(smem + S_OFF_HL + boff) = lo;
            }
        } else {
            // Pure copy: 16 rows x 512 bf16 per plane = 64 uint4 per row
            const uint4* hh = (const uint4*)(g_hh[s & 1] + (size_t)b0 * 512);
            const uint4* hl = (const uint4*)(g_hl[s & 1] + (size_t)b0 * 512);
#pragma unroll
            for (int i = 0; i < 4; i++) {
                int idx = t + 256 * i;       // 0..1023
                int row = idx >> 6;          // 0..15
                int q   = idx & 63;
                uint32_t boff = (uint32_t)(row * SPITCH) * 2 + q * 16;
                *(uint4*)(smem + S_OFF_HH + boff) = hh[row * 64 + q];
                *(uint4*)(smem + S_OFF_HL + boff) = hl[row * 64 + q];
            }
        }

        // --- Prefetch gi / f (independent of MMA) ---
        size_t gib = ((size_t)s * 64 + bglob) * 1536 + c0 + ej;
        float i_r = g_gi[gib];
        float i_i = g_gi[gib + 512];
        float i_n = g_gi[gib + 1024];
        size_t fb = ((size_t)s * 64 + bglob) * 1024 + c0 + ej;
        float f_r = g_f[fb];
        float f_i = g_f[fb + 512];

        __syncthreads();   // h planes visible

        // --- MMA phase: gh partial over warp's K-slice (64) ---
        float acc[6][4];
#pragma unroll
        for (int nj = 0; nj < 6; nj++)
#pragma unroll
            for (int k = 0; k < 4; k++) acc[nj][k] = 0.f;

#pragma unroll
        for (int ks = 0; ks < 4; ks++) {
            uint32_t ah[4], al[4];
            int arow = lr + (lg & 1) * 8;
            int acol = w * 64 + ks * 16 + (lg >> 1) * 8;
            uint32_t aoff = (uint32_t)(arow * SPITCH + acol) * 2;
            LDMATRIX_X4(ah, sb + S_OFF_HH + aoff);
            LDMATRIX_X4(al, sb + S_OFF_HL + aoff);
#pragma unroll
            for (int np = 0; np < 3; np++)
#pragma unroll
                for (int sub = 0; sub < 2; sub++) {
                    int nj = np * 2 + sub;
                    MMA_BF16(acc[nj], ah, bfh[np][ks][2 * sub], bfh[np][ks][2 * sub + 1]);
                    MMA_BF16(acc[nj], ah, bfl[np][ks][2 * sub], bfl[np][ks][2 * sub + 1]);
                    MMA_BF16(acc[nj], al, bfh[np][ks][2 * sub], bfh[np][ks][2 * sub + 1]);
                }
        }

        // --- Store partials [m16 x n48], pitch 49 ---
        {
            float* red = redf + w * 784;
#pragma unroll
            for (int nj = 0; nj < 6; nj++)
#pragma unroll
                for (int half = 0; half < 2; half++) {
                    int m = qrow + half * 8;
                    int n = nj * 8 + qcol;
                    red[m * 49 + n]     = acc[nj][half * 2 + 0];
                    red[m * 49 + n + 1] = acc[nj][half * 2 + 1];
                }
        }
        __syncthreads();

        // --- Fused reduce + gate epilogue for (eb, ej) ---
        float h_r = bs[ej];
        float h_i = bs[16 + ej];
        float h_n = bs[32 + ej];
#pragma unroll
        for (int w2 = 0; w2 < 8; w2++) {
            const float* rr = redf + w2 * 784 + eb * 49;
            h_r += rr[ej];
            h_i += rr[16 + ej];
            h_n += rr[32 + ej];
        }
        float rgate = 1.f / (1.f + __expf(-(i_r + h_r + f_r)));
        float igate = 1.f / (1.f + __expf(-(i_i + h_i + f_i)));
        float ngate = tanhf(i_n + rgate * h_n);
        float hy = ngate + igate * (hprev - ngate);
        hprev = hy;

        // h for next step, hi/lo planes (conversion at the producer)
        {
            __nv_bfloat16 hhi = __float2bfloat16_rn(hy);
            float resid = hy - __bfloat162float(hhi);
            __nv_bfloat16 hlo = __float2bfloat16_rn(resid);
            size_t hidx = (size_t)bglob * 512 + c0 + ej;
            g_hh[(s + 1) & 1][hidx] = hhi;
            g_hl[(s + 1) & 1][hidx] = hlo;
        }

        __syncthreads();                   // all hy stores issued
        if (t == 0) {
            asm volatile("red.release.gpu.global.add.u32 [%0], %1;"
                         :: "l"(barp), "r"(1u) : "memory");
        }

        // out-row store overlaps other CTAs' barrier arrival
        out[((size_t)bglob * 512 + s) * 512 + c0 + ej] = hy;
        if (s == 511)
            out[(size_t)64 * 512 * 512 + (size_t)bglob * 512 + c0 + ej] = hy;

        if (t == 0) {
            unsigned target = (unsigned)(s + 1) * 32u;
            unsigned v;
            do {
                asm volatile("ld.acquire.gpu.global.u32 %0, [%1];"
                             : "=r"(v) : "l"(barp) : "memory");
            } while (v < target);
        }
        __syncthreads();
    }
}

// ---------------------------------------------------------------------------
// Launch
// ---------------------------------------------------------------------------
extern "C" void kernel_launch(void* const* d_in, const int* in_sizes, int n_in,
                              void* d_out, int out_size) {
    const float* input = (const float*)d_in[0];   // [B,S,D]
    const float* aux   = (const float*)d_in[1];   // [2,B,S,D]
    const float* hx    = (const float*)d_in[2];   // [B,H]
    const float* w_ih  = (const float*)d_in[3];   // [3H,D]
    const float* w_fh  = (const float*)d_in[4];   // [2,2H,D]
    const float* b_ih  = (const float*)d_in[5];   // [3H]
    const float* b_fh  = (const float*)d_in[6];   // [2,2H]
    const float* w_hh  = (const float*)d_in[7];   // [3H,H]
    const float* b_hh  = (const float*)d_in[8];   // [3H]
    float* out = (float*)d_out;

    cudaFuncSetAttribute(gemm_gi_mma,
                         cudaFuncAttributeMaxDynamicSharedMemorySize,
                         GEMM_SMEM_BYTES);
    cudaFuncSetAttribute(gemm_f_mma,
                         cudaFuncAttributeMaxDynamicSharedMemorySize,
                         GEMM_SMEM_BYTES);
    cudaFuncSetAttribute(scan_kernel,
                         cudaFuncAttributeMaxDynamicSharedMemorySize,
                         SCAN_SMEM_BYTES);

    // n-tile fastest (x), m-tile slow (y). M tiles of 256 -> grid.y = 128.
    gemm_gi_mma<<<dim3(12, 128), 512, GEMM_SMEM_BYTES>>>(input, w_ih, b_ih);
    gemm_f_mma<<<dim3(8, 128), 512, GEMM_SMEM_BYTES>>>(aux, w_fh, b_fh);
    scan_kernel<<<128, 256, SCAN_SMEM_BYTES>>>(hx, w_hh, b_hh, out);
}

// round 17
// speedup vs baseline: 1.1433x; 1.1433x over previous
#include <cuda_runtime.h>
#include <cuda_bf16.h>
#include <math.h>
#include <stdint.h>

// Problem sizes (fixed)
#define BB 64     // batch
#define SS 512    // seq len
#define DD 512    // input dim
#define HH 512    // hidden

// ---------------------------------------------------------------------------
// Device scratch (allocation-free rule: device globals only)
// ---------------------------------------------------------------------------
__device__ float g_gi[(size_t)SS * BB * 3 * HH];   // [s][b][3H]
__device__ float g_f [(size_t)SS * BB * 2 * HH];   // [s][b][2H]
__device__ __nv_bfloat16 g_hh[2][BB * HH];         // h hi-plane ping-pong
__device__ __nv_bfloat16 g_hl[2][BB * HH];         // h lo-plane ping-pong
__device__ unsigned g_bar[4];                      // per-batch-group barrier

// ---------------------------------------------------------------------------
// mma.sync helpers (sm_80+ vocabulary — works under compute_103 PTX)
// ---------------------------------------------------------------------------
__device__ __forceinline__ uint32_t smem_to_u32(const void* p) {
    uint32_t a;
    asm("{ .reg .u64 t; cvta.to.shared.u64 t, %1; cvt.u32.u64 %0, t; }"
        : "=r"(a) : "l"(p));
    return a;
}

#define LDMATRIX_X4(r, addr) \
    asm volatile("ldmatrix.sync.aligned.m8n8.x4.shared.b16 {%0,%1,%2,%3}, [%4];" \
        : "=r"((r)[0]), "=r"((r)[1]), "=r"((r)[2]), "=r"((r)[3]) : "r"(addr))

#define MMA_BF16(d, a, b0, b1) \
    asm volatile("mma.sync.aligned.m16n8k16.row.col.f32.bf16.bf16.f32 " \
        "{%0,%1,%2,%3}, {%4,%5,%6,%7}, {%8,%9}, {%0,%1,%2,%3};" \
        : "+f"((d)[0]), "+f"((d)[1]), "+f"((d)[2]), "+f"((d)[3]) \
        : "r"((a)[0]), "r"((a)[1]), "r"((a)[2]), "r"((a)[3]), \
          "r"(b0), "r"(b1))

__device__ __forceinline__ uint32_t pack_bf16(float a, float b) {
    return ((uint32_t)__bfloat16_as_ushort(__float2bfloat16_rn(b)) << 16) |
           (uint32_t)__bfloat16_as_ushort(__float2bfloat16_rn(a));
}

// ---------------------------------------------------------------------------
// Precompute GEMMs: CTA 128(M)x256(N), BK=64, 256 threads (8 warps, 2x4 warp
// grid, warp tile 64x64 -> 16 LDSM.x4 : 96 MMA, halving LDSM per MMA vs the
// 64x32 tile). bf16 hi/lo 3-pass split. Double-buffered, one sync per chunk;
// prefetch time-sliced (A, B-half0, B-half1) to bound live registers.
// ---------------------------------------------------------------------------
#define GP2 72                             // smem pitch in bf16 (144 B rows)
#define GA_TILE_B (128 * GP2 * 2)          // 18432 (A hi or lo)
#define GB_TILE_B (256 * GP2 * 2)          // 36864 (B hi or lo)
#define STG_B (2 * GA_TILE_B + 2 * GB_TILE_B)  // 110592 per stage
#define OFF_AH3(st) ((st) * STG_B)
#define OFF_AL3(st) ((st) * STG_B + GA_TILE_B)
#define OFF_BH3(st) ((st) * STG_B + 2 * GA_TILE_B)
#define OFF_BL3(st) ((st) * STG_B + 2 * GA_TILE_B + GB_TILE_B)
#define GEMM_SMEM_BYTES (2 * STG_B)        // 221184

// Load a [128 x 64] fp32 block (row stride 512): 8 float4 per thread @256thr.
__device__ __forceinline__ void ldg_128(const float* __restrict__ src,
                                        float4 v[8], int t) {
#pragma unroll
    for (int i = 0; i < 8; i++) {
        int idx = t + 256 * i;
        int row = idx >> 4;
        int kq  = idx & 15;
        v[i] = *(const float4*)(src + (size_t)row * 512 + kq * 4);
    }
}

__device__ __forceinline__ void cvt_store(char* smem, int hi_off, int lo_off,
                                          float4 x, int row, int kq) {
    float hx = __bfloat162float(__float2bfloat16_rn(x.x));
    float hy = __bfloat162float(__float2bfloat16_rn(x.y));
    float hz = __bfloat162float(__float2bfloat16_rn(x.z));
    float hw = __bfloat162float(__float2bfloat16_rn(x.w));
    uint2 hi = make_uint2(pack_bf16(x.x, x.y), pack_bf16(x.z, x.w));
    uint2 lo = make_uint2(pack_bf16(x.x - hx, x.y - hy),
                          pack_bf16(x.z - hz, x.w - hw));
    uint32_t boff = (uint32_t)(row * GP2 + kq * 4) * 2;
    *(uint2*)(smem + hi_off + boff) = hi;
    *(uint2*)(smem + lo_off + boff) = lo;
}

// Store a 128-row block into hi/lo tiles with row offset row0.
__device__ __forceinline__ void sts_128(char* smem, int hi_off, int lo_off,
                                        const float4 v[8], int t, int row0) {
#pragma unroll
    for (int i = 0; i < 8; i++) {
        int idx = t + 256 * i;
        cvt_store(smem, hi_off, lo_off, v[i], row0 + (idx >> 4), idx & 15);
    }
}

// One k16 step: warp tile 64(M) x 64(N): 16 ldmatrix.x4 + 96 mma.
__device__ __forceinline__ void warp_k16(uint32_t sb, int st, int ks,
                                         int wm, int wn, int lane,
                                         float acc[4][8][4]) {
    const int lr = lane & 7;
    const int lg = lane >> 3;
    uint32_t ah[4][4], al[4][4];
#pragma unroll
    for (int mt = 0; mt < 4; mt++) {
        int arow = wm * 64 + mt * 16 + lr + (lg & 1) * 8;
        int acol = ks * 16 + (lg >> 1) * 8;
        uint32_t boff = (uint32_t)(arow * GP2 + acol) * 2;
        LDMATRIX_X4(ah[mt], sb + OFF_AH3(st) + boff);
        LDMATRIX_X4(al[mt], sb + OFF_AL3(st) + boff);
    }
    uint32_t bh[4][4], bl[4][4];
#pragma unroll
    for (int np = 0; np < 4; np++) {
        int brow = wn * 64 + np * 16 + lr + (lg >> 1) * 8;
        int bcol = ks * 16 + (lg & 1) * 8;
        uint32_t boff = (uint32_t)(brow * GP2 + bcol) * 2;
        LDMATRIX_X4(bh[np], sb + OFF_BH3(st) + boff);
        LDMATRIX_X4(bl[np], sb + OFF_BL3(st) + boff);
    }
#pragma unroll
    for (int mt = 0; mt < 4; mt++)
#pragma unroll
        for (int np = 0; np < 4; np++)
#pragma unroll
            for (int sub = 0; sub < 2; sub++) {
                int nj = np * 2 + sub;
                MMA_BF16(acc[mt][nj], ah[mt], bh[np][2 * sub], bh[np][2 * sub + 1]);
                MMA_BF16(acc[mt][nj], ah[mt], bl[np][2 * sub], bl[np][2 * sub + 1]);
                MMA_BF16(acc[mt][nj], al[mt], bh[np][2 * sub], bh[np][2 * sub + 1]);
            }
}

__global__ __launch_bounds__(256, 1) void gemm_gi_mma(
    const float* __restrict__ A, const float* __restrict__ W,
    const float* __restrict__ bias)
{
    extern __shared__ char smem[];
    uint32_t sb = smem_to_u32(smem);
    const int t = threadIdx.x;
    const int wid = t >> 5;
    const int lane = t & 31;
    const int wm = wid & 1;            // 2 m-warps x 64 = 128
    const int wn = wid >> 1;           // 4 n-warps x 64 = 256
    const int m0 = blockIdx.y * 128;   // n fastest: x = n-tile, y = m-tile
    const int n0 = blockIdx.x * 256;

    // Zero the scan's group barrier (replaces the init kernel).
    if (blockIdx.x == 0 && blockIdx.y == 0 && t < 4) g_bar[t] = 0u;

    float acc[4][8][4];
#pragma unroll
    for (int i = 0; i < 4; i++)
#pragma unroll
        for (int j = 0; j < 8; j++)
#pragma unroll
            for (int k = 0; k < 4; k++) acc[i][j][k] = 0.f;

    const float* Abase = A + (size_t)m0 * 512;
    const float* Wbase = W + (size_t)n0 * 512;

    float4 pf[8];
    // Fill stage 0 (chunk 0: K 0..63)
    ldg_128(Abase, pf, t);
    sts_128(smem, OFF_AH3(0), OFF_AL3(0), pf, t, 0);
    ldg_128(Wbase, pf, t);
    sts_128(smem, OFF_BH3(0), OFF_BL3(0), pf, t, 0);
    ldg_128(Wbase + (size_t)128 * 512, pf, t);
    sts_128(smem, OFF_BH3(0), OFF_BL3(0), pf, t, 128);
    __syncthreads();

    const int NC = 8;   // 512 / 64
    for (int c = 0; c < NC; c++) {
        int st = c & 1;
        int ns = st ^ 1;
        bool more = (c + 1 < NC);
        const float* An = Abase + (c + 1) * 64;
        const float* Wn = Wbase + (c + 1) * 64;

        warp_k16(sb, st, 0, wm, wn, lane, acc);
        if (more) ldg_128(An, pf, t);
        warp_k16(sb, st, 1, wm, wn, lane, acc);
        if (more) {
            sts_128(smem, OFF_AH3(ns), OFF_AL3(ns), pf, t, 0);
            ldg_128(Wn, pf, t);
        }
        warp_k16(sb, st, 2, wm, wn, lane, acc);
        if (more) {
            sts_128(smem, OFF_BH3(ns), OFF_BL3(ns), pf, t, 0);
            ldg_128(Wn + (size_t)128 * 512, pf, t);
        }
        warp_k16(sb, st, 3, wm, wn, lane, acc);
        if (more) sts_128(smem, OFF_BH3(ns), OFF_BL3(ns), pf, t, 128);
        __syncthreads();
    }

    const int qrow = lane >> 2;
    const int qcol = (lane & 3) * 2;
#pragma unroll
    for (int mt = 0; mt < 4; mt++)
#pragma unroll
        for (int half = 0; half < 2; half++) {
            int m = m0 + wm * 64 + mt * 16 + qrow + half * 8;
            int b = m >> 9;
            int s = m & 511;
            float* crow = &g_gi[((size_t)s * 64 + b) * 1536 + n0 + wn * 64];
#pragma unroll
            for (int nj = 0; nj < 8; nj++) {
                int n = nj * 8 + qcol;
                float2 bvv = *(const float2*)&bias[n0 + wn * 64 + n];
                float2 o;
                o.x = acc[mt][nj][half * 2 + 0] + bvv.x;
                o.y = acc[mt][nj][half * 2 + 1] + bvv.y;
                *(float2*)&crow[n] = o;
            }
        }
}

__global__ __launch_bounds__(256, 1) void gemm_f_mma(
    const float* __restrict__ Aux, const float* __restrict__ Wf,
    const float* __restrict__ bf)
{
    extern __shared__ char smem[];
    uint32_t sb = smem_to_u32(smem);
    const int t = threadIdx.x;
    const int wid = t >> 5;
    const int lane = t & 31;
    const int wm = wid & 1;
    const int wn = wid >> 1;
    const int m0 = blockIdx.y * 128;   // n fastest
    const int n0 = blockIdx.x * 256;

    float acc[4][8][4];
#pragma unroll
    for (int i = 0; i < 4; i++)
#pragma unroll
        for (int j = 0; j < 8; j++)
#pragma unroll
            for (int k = 0; k < 4; k++) acc[i][j][k] = 0.f;

    float4 pf[8];
    const float* A0 = Aux + (size_t)m0 * 512;
    const float* W0 = Wf + (size_t)n0 * 512;
    ldg_128(A0, pf, t);
    sts_128(smem, OFF_AH3(0), OFF_AL3(0), pf, t, 0);
    ldg_128(W0, pf, t);
    sts_128(smem, OFF_BH3(0), OFF_BL3(0), pf, t, 0);
    ldg_128(W0 + (size_t)128 * 512, pf, t);
    sts_128(smem, OFF_BH3(0), OFF_BL3(0), pf, t, 128);
    __syncthreads();

    const int NC = 16;  // 2 segments x 8 chunks of 64K
    for (int c = 0; c < NC; c++) {
        int st = c & 1;
        int ns = st ^ 1;
        bool more = (c + 1 < NC);
        int cn = c + 1;
        int seg = cn >> 3, kk = cn & 7;
        const float* An = Aux + (size_t)seg * 32768 * 512 + (size_t)m0 * 512 + kk * 64;
        const float* Wn = Wf + (size_t)seg * 1024 * 512 + (size_t)n0 * 512 + kk * 64;

        warp_k16(sb, st, 0, wm, wn, lane, acc);
        if (more) ldg_128(An, pf, t);
        warp_k16(sb, st, 1, wm, wn, lane, acc);
        if (more) {
            sts_128(smem, OFF_AH3(ns), OFF_AL3(ns), pf, t, 0);
            ldg_128(Wn, pf, t);
        }
        warp_k16(sb, st, 2, wm, wn, lane, acc);
        if (more) {
            sts_128(smem, OFF_BH3(ns), OFF_BL3(ns), pf, t, 0);
            ldg_128(Wn + (size_t)128 * 512, pf, t);
        }
        warp_k16(sb, st, 3, wm, wn, lane, acc);
        if (more) sts_128(smem, OFF_BH3(ns), OFF_BL3(ns), pf, t, 128);
        __syncthreads();
    }

    const int qrow = lane >> 2;
    const int qcol = (lane & 3) * 2;
#pragma unroll
    for (int mt = 0; mt < 4; mt++)
#pragma unroll
        for (int half = 0; half < 2; half++) {
            int m = m0 + wm * 64 + mt * 16 + qrow + half * 8;
            int b = m >> 9;
            int s = m & 511;
            float* crow = &g_f[((size_t)s * 64 + b) * 1024 + n0 + wn * 64];
#pragma unroll
            for (int nj = 0; nj < 8; nj++) {
                int n = nj * 8 + qcol;
                int ng = n0 + wn * 64 + n;
                float2 c0 = *(const float2*)&bf[ng];
                float2 c1 = *(const float2*)&bf[1024 + ng];
                float2 o;
                o.x = 0.5f * acc[mt][nj][half * 2 + 0] + 0.5f * (c0.x + c1.x);
                o.y = 0.5f * acc[mt][nj][half * 2 + 1] + 0.5f * (c0.y + c1.y);
                *(float2*)&crow[n] = o;
            }
        }
}

// ---------------------------------------------------------------------------
// Persistent recurrent scan — byte-identical to the round-12 best:
// 256 threads, producer-side bf16 hi/lo h exchange, fused reduce+epilogue,
// t0-spin barrier with __syncthreads detection broadcast.
// Grid 128 = 4 batch-groups (16 b) x 32 column-CTAs (16 hy cols = 48 W rows).
// ---------------------------------------------------------------------------
#define SPITCH 520                       // bf16 pitch
#define S_OFF_WH  0                      // 48 x 520 bf16 = 49920 B
#define S_OFF_WL  49920
#define S_OFF_HH  99840                  // 16 x 520 bf16 = 16640 B
#define S_OFF_HL  116480
#define S_OFF_RED 133120                 // 8 x 784 fp32 = 25088 B
#define S_OFF_BS  158208                 // 48 fp32
#define SCAN_SMEM_BYTES 158400

__global__ __launch_bounds__(256, 1) void scan_kernel(
    const float* __restrict__ hx, const float* __restrict__ Whh,
    const float* __restrict__ bias_hh, float* __restrict__ out)
{
    extern __shared__ char smem[];
    uint32_t sb = smem_to_u32(smem);
    float* redf = (float*)(smem + S_OFF_RED);
    float* bs   = (float*)(smem + S_OFF_BS);

    const int t    = threadIdx.x;
    const int w    = t >> 5;               // warp 0..7 (K-slice 64 each)
    const int lane = t & 31;
    const int lr   = lane & 7;
    const int lg   = lane >> 3;
    const int gid  = blockIdx.x >> 5;
    const int cid  = blockIdx.x & 31;
    const int b0   = gid * 16;
    const int c0   = cid * 16;

    // --- Stage W_hh slice as bf16 hi/lo into smem (once) ---
    for (int i = t; i < 48 * 128; i += 256) {
        int r = i >> 7;
        int q = i & 127;
        int gate = r >> 4, j = r & 15;
        float4 v = *(const float4*)&Whh[(size_t)(gate * 512 + c0 + j) * 512 + q * 4];
        float hx0 = __bfloat162float(__float2bfloat16_rn(v.x));
        float hy0 = __bfloat162float(__float2bfloat16_rn(v.y));
        float hz0 = __bfloat162float(__float2bfloat16_rn(v.z));
        float hw0 = __bfloat162float(__float2bfloat16_rn(v.w));
        uint2 hi = make_uint2(pack_bf16(v.x, v.y), pack_bf16(v.z, v.w));
        uint2 lo = make_uint2(pack_bf16(v.x - hx0, v.y - hy0),
                              pack_bf16(v.z - hz0, v.w - hw0));
        uint32_t boff = (uint32_t)(r * SPITCH + q * 4) * 2;
        *(uint2*)(smem + S_OFF_WH + boff) = hi;
        *(uint2*)(smem + S_OFF_WL + boff) = lo;
    }
    if (t < 48) {
        int gate = t >> 4, j = t & 15;
        bs[t] = bias_hh[gate * 512 + c0 + j];
    }
    __syncthreads();

    // --- W fragments in registers: per warp 3 n16-groups x 4 k16 (hi/lo) ---
    uint32_t bfh[3][4][4], bfl[3][4][4];
#pragma unroll
    for (int np = 0; np < 3; np++)
#pragma unroll
        for (int ks = 0; ks < 4; ks++) {
            int brow = np * 16 + lr + (lg >> 1) * 8;
            int bcol = w * 64 + ks * 16 + (lg & 1) * 8;
            uint32_t boff = (uint32_t)(brow * SPITCH + bcol) * 2;
            LDMATRIX_X4(bfh[np][ks], sb + S_OFF_WH + boff);
            LDMATRIX_X4(bfl[np][ks], sb + S_OFF_WL + boff);
        }

    const int eb = t >> 4;                 // epilogue batch 0..15
    const int ej = t & 15;                 // epilogue column 0..15
    const int bglob = b0 + eb;
    const int qrow = lane >> 2;
    const int qcol = (lane & 3) * 2;

    unsigned* barp = &g_bar[gid];

    // hprev carried in register (exact fp32): this thread owns (bglob, c0+ej)
    float hprev = hx[(size_t)bglob * 512 + c0 + ej];

    for (int s = 0; s < 512; s++) {
        if (s == 0) {
            // One-time: convert hx (fp32) into hi/lo planes in smem
            const float* hsrc = hx + (size_t)b0 * 512;
#pragma unroll
            for (int i = 0; i < 8; i++) {
                int idx = t + 256 * i;
                int row = idx >> 7;
                int q   = idx & 127;
                float4 v = *(const float4*)&hsrc[(size_t)row * 512 + q * 4];
                float hx0 = __bfloat162float(__float2bfloat16_rn(v.x));
                float hy0 = __bfloat162float(__float2bfloat16_rn(v.y));
                float hz0 = __bfloat162float(__float2bfloat16_rn(v.z));
                float hw0 = __bfloat162float(__float2bfloat16_rn(v.w));
                uint2 hi = make_uint2(pack_bf16(v.x, v.y), pack_bf16(v.z, v.w));
                uint2 lo = make_uint2(pack_bf16(v.x - hx0, v.y - hy0),
                                      pack_bf16(v.z - hz0, v.w - hw0));
                uint32_t boff = (uint32_t)(row * SPITCH + q * 4) * 2;
                *(uint2*)(smem + S_OFF_HH + boff) = hi;
                *(uint2*)(smem + S_OFF_HL + boff) = lo;
            }
        } else {
            // Pure copy: 16 rows x 512 bf16 per plane = 64 uint4 per row
            const uint4* hh = (const uint4*)(g_hh[s & 1] + (size_t)b0 * 512);
            const uint4* hl = (const uint4*)(g_hl[s & 1] + (size_t)b0 * 512);
#pragma unroll
            for (int i = 0; i < 4; i++) {
                int idx = t + 256 * i;       // 0..1023
                int row = idx >> 6;          // 0..15
                int q   = idx & 63;
                uint32_t boff = (uint32_t)(row * SPITCH) * 2 + q * 16;
                *(uint4*)(smem + S_OFF_HH + boff) = hh[row * 64 + q];
                *(uint4*)(smem + S_OFF_HL + boff) = hl[row * 64 + q];
            }
        }

        // --- Prefetch gi / f (independent of MMA) ---
        size_t gib = ((size_t)s * 64 + bglob) * 1536 + c0 + ej;
        float i_r = g_gi[gib];
        float i_i = g_gi[gib + 512];
        float i_n = g_gi[gib + 1024];
        size_t fb = ((size_t)s * 64 + bglob) * 1024 + c0 + ej;
        float f_r = g_f[fb];
        float f_i = g_f[fb + 512];

        __syncthreads();   // h planes visible

        // --- MMA phase: gh partial over warp's K-slice (64) ---
        float acc[6][4];
#pragma unroll
        for (int nj = 0; nj < 6; nj++)
#pragma unroll
            for (int k = 0; k < 4; k++) acc[nj][k] = 0.f;

#pragma unroll
        for (int ks = 0; ks < 4; ks++) {
            uint32_t ah[4], al[4];
            int arow = lr + (lg & 1) * 8;
            int acol = w * 64 + ks * 16 + (lg >> 1) * 8;
            uint32_t aoff = (uint32_t)(arow * SPITCH + acol) * 2;
            LDMATRIX_X4(ah, sb + S_OFF_HH + aoff);
            LDMATRIX_X4(al, sb + S_OFF_HL + aoff);
#pragma unroll
            for (int np = 0; np < 3; np++)
#pragma unroll
                for (int sub = 0; sub < 2; sub++) {
                    int nj = np * 2 + sub;
                    MMA_BF16(acc[nj], ah, bfh[np][ks][2 * sub], bfh[np][ks][2 * sub + 1]);
                    MMA_BF16(acc[nj], ah, bfl[np][ks][2 * sub], bfl[np][ks][2 * sub + 1]);
                    MMA_BF16(acc[nj], al, bfh[np][ks][2 * sub], bfh[np][ks][2 * sub + 1]);
                }
        }

        // --- Store partials [m16 x n48], pitch 49 ---
        {
            float* red = redf + w * 784;
#pragma unroll
            for (int nj = 0; nj < 6; nj++)
#pragma unroll
                for (int half = 0; half < 2; half++) {
                    int m = qrow + half * 8;
                    int n = nj * 8 + qcol;
                    red[m * 49 + n]     = acc[nj][half * 2 + 0];
                    red[m * 49 + n + 1] = acc[nj][half * 2 + 1];
                }
        }
        __syncthreads();

        // --- Fused reduce + gate epilogue for (eb, ej) ---
        float h_r = bs[ej];
        float h_i = bs[16 + ej];
        float h_n = bs[32 + ej];
#pragma unroll
        for (int w2 = 0; w2 < 8; w2++) {
            const float* rr = redf + w2 * 784 + eb * 49;
            h_r += rr[ej];
            h_i += rr[16 + ej];
            h_n += rr[32 + ej];
        }
        float rgate = 1.f / (1.f + __expf(-(i_r + h_r + f_r)));
        float igate = 1.f / (1.f + __expf(-(i_i + h_i + f_i)));
        float ngate = tanhf(i_n + rgate * h_n);
        float hy = ngate + igate * (hprev - ngate);
        hprev = hy;

        // h for next step, hi/lo planes (conversion at the producer)
        {
            __nv_bfloat16 hhi = __float2bfloat16_rn(hy);
            float resid = hy - __bfloat162float(hhi);
            __nv_bfloat16 hlo = __float2bfloat16_rn(resid);
            size_t hidx = (size_t)bglob * 512 + c0 + ej;
            g_hh[(s + 1) & 1][hidx] = hhi;
            g_hl[(s + 1) & 1][hidx] = hlo;
        }

        __syncthreads();                   // all hy stores issued
        if (t == 0) {
            asm volatile("red.release.gpu.global.add.u32 [%0], %1;"
                         :: "l"(barp), "r"(1u) : "memory");
        }

        // out-row store overlaps other CTAs' barrier arrival
        out[((size_t)bglob * 512 + s) * 512 + c0 + ej] = hy;
        if (s == 511)
            out[(size_t)64 * 512 * 512 + (size_t)bglob * 512 + c0 + ej] = hy;

        if (t == 0) {
            unsigned target = (unsigned)(s + 1) * 32u;
            unsigned v;
            do {
                asm volatile("ld.acquire.gpu.global.u32 %0, [%1];"
                             : "=r"(v) : "l"(barp) : "memory");
            } while (v < target);
        }
        __syncthreads();
    }
}

// ---------------------------------------------------------------------------
// Launch
// ---------------------------------------------------------------------------
extern "C" void kernel_launch(void* const* d_in, const int* in_sizes, int n_in,
                              void* d_out, int out_size) {
    const float* input = (const float*)d_in[0];   // [B,S,D]
    const float* aux   = (const float*)d_in[1];   // [2,B,S,D]
    const float* hx    = (const float*)d_in[2];   // [B,H]
    const float* w_ih  = (const float*)d_in[3];   // [3H,D]
    const float* w_fh  = (const float*)d_in[4];   // [2,2H,D]
    const float* b_ih  = (const float*)d_in[5];   // [3H]
    const float* b_fh  = (const float*)d_in[6];   // [2,2H]
    const float* w_hh  = (const float*)d_in[7];   // [3H,H]
    const float* b_hh  = (const float*)d_in[8];   // [3H]
    float* out = (float*)d_out;

    cudaFuncSetAttribute(gemm_gi_mma,
                         cudaFuncAttributeMaxDynamicSharedMemorySize,
                         GEMM_SMEM_BYTES);
    cudaFuncSetAttribute(gemm_f_mma,
                         cudaFuncAttributeMaxDynamicSharedMemorySize,
                         GEMM_SMEM_BYTES);
    cudaFuncSetAttribute(scan_kernel,
                         cudaFuncAttributeMaxDynamicSharedMemorySize,
                         SCAN_SMEM_BYTES);

    // n-tile fastest (x), m-tile slow (y). N tiles of 256: gi 6, f 4.
    gemm_gi_mma<<<dim3(6, 256), 256, GEMM_SMEM_BYTES>>>(input, w_ih, b_ih);
    gemm_f_mma<<<dim3(4, 256), 256, GEMM_SMEM_BYTES>>>(aux, w_fh, b_fh);
    scan_kernel<<<128, 256, SCAN_SMEM_BYTES>>>(hx, w_hh, b_hh, out);
}